// round 15
// baseline (speedup 1.0000x reference)
#include <cuda_runtime.h>
#include <cuda_bf16.h>
#include <math.h>
#include <stdint.h>

// Problem dims
#define PB 64
#define PT 1024
#define PE 256
#define PU 1024
#define PC3 3072
#define PV 32000

#define NBLK 128
#define TILE_U 8          // u per block; N = 24 cols (3 gates x 8 u)
#define TPB 256           // 8 warps
#define NCOL 24
#define KCHUNK 256        // k per staged A chunk (scan)
#define NCHNK (PU / KCHUNK)
#define AROWB 528         // scan A smem row stride bytes
#define ABUFB (128 * AROWB)
#define WLOST 1032        // Wlo smem row stride (bf16 elems)
#define DPST 26           // Dp row stride (floats), conflict-reduced

// scan smem byte offsets
#define SM_A     0
#define SM_WLO   (2 * ABUFB)             // 135168
#define SM_OS    184704
#define SM_OSH   186752
#define SM_OSL   187776
#define SM_BRS   188800
#define SM_TOTAL 188928
// Dp overlays A buffers: 1024 * DPST * 4 = 106496 <= 135168

// inproj-mma smem
#define IP_BUF   40960
#define IP_TOTAL (2 * IP_BUF)
#define IPROW 80

// ---------------------------------------------------------------------------
// global scratch
// ---------------------------------------------------------------------------
__device__ float g_xp[(size_t)PT * PB * PC3];
__device__ __nv_bfloat16 g_hhi[2][PB * PU];
__device__ __nv_bfloat16 g_hlo[2][PB * PU];
__device__ __nv_bfloat16 g_embh[(size_t)PV * PE];
__device__ __nv_bfloat16 g_embl[(size_t)PV * PE];
__device__ __nv_bfloat16 g_winth[(size_t)PC3 * PE];
__device__ __nv_bfloat16 g_wintl[(size_t)PC3 * PE];

// chunk-ready counters (monotonic; reset each launch by k_split_init).
// cnt[c*32]: number of per-block publishes of u-slices in k-chunk c.
// 32 owning blocks per chunk -> chunk c of step t ready when cnt >= 32*t.
__device__ unsigned g_ck[NCHNK * 32];

// ---------------------------------------------------------------------------
// PTX wrappers (baseline PTX, valid on compute_103)
// ---------------------------------------------------------------------------
__device__ __forceinline__ uint32_t smem_u32(const void* p) {
    uint32_t a;
    asm("{ .reg .u64 t; cvta.to.shared.u64 t, %1; cvt.u32.u64 %0, t; }" : "=r"(a) : "l"(p));
    return a;
}
__device__ __forceinline__ void mma_bf16(float* d, const uint32_t* a, const uint32_t* b) {
    asm volatile(
        "mma.sync.aligned.m16n8k16.row.col.f32.bf16.bf16.f32 "
        "{%0,%1,%2,%3}, {%4,%5,%6,%7}, {%8,%9}, {%0,%1,%2,%3};"
        : "+f"(d[0]), "+f"(d[1]), "+f"(d[2]), "+f"(d[3])
        : "r"(a[0]), "r"(a[1]), "r"(a[2]), "r"(a[3]), "r"(b[0]), "r"(b[1]));
}
__device__ __forceinline__ void ldsm_x4(uint32_t* r, uint32_t addr) {
    asm volatile("ldmatrix.sync.aligned.m8n8.x4.shared.b16 {%0,%1,%2,%3}, [%4];"
                 : "=r"(r[0]), "=r"(r[1]), "=r"(r[2]), "=r"(r[3]) : "r"(addr));
}
__device__ __forceinline__ void cp16(uint32_t dst, const void* src) {
    asm volatile("cp.async.cg.shared.global [%0], [%1], 16;" :: "r"(dst), "l"(src));
}
__device__ __forceinline__ void cp_commit() { asm volatile("cp.async.commit_group;" ::: "memory"); }
__device__ __forceinline__ void cp_wait0()  { asm volatile("cp.async.wait_group 0;" ::: "memory"); }
__device__ __forceinline__ uint32_t pack_bf16x2(float lo, float hi) {
    __nv_bfloat162 v = __floats2bfloat162_rn(lo, hi);
    return *(uint32_t*)&v;
}
__device__ __forceinline__ float sig_fast(float v) {
    return 1.0f / (1.0f + __expf(-v));
}
__device__ __forceinline__ float tanh_fast(float v) {
    float ax = fabsf(v);
    float e  = __expf(2.0f * ax);
    float t  = 1.0f - 2.0f / (e + 1.0f);
    return copysignf(t, v);
}
// all threads spin until chunk c of step t is published (target = 32*t)
__device__ __forceinline__ void wait_chunk(int c, unsigned target) {
    if (target == 0u) return;
    volatile unsigned* p = &g_ck[c * 32];
    while (*p < target) { }
    __threadfence();
}

// ---------------------------------------------------------------------------
// prep kernels
// ---------------------------------------------------------------------------
__global__ void k_split_init(const float* __restrict__ h0,
                             __nv_bfloat16* __restrict__ hi,
                             __nv_bfloat16* __restrict__ lo) {
    int idx = blockIdx.x * blockDim.x + threadIdx.x;
    if (idx < PB * PU) {
        float v = h0[idx];
        __nv_bfloat16 h = __float2bfloat16_rn(v);
        hi[idx] = h;
        lo[idx] = __float2bfloat16_rn(v - __bfloat162float(h));
    }
    // reset chunk counters EVERY launch (graph replays reuse the globals);
    // guard fully covered by block 0's 256 threads.
    if (blockIdx.x == 0 && threadIdx.x < NCHNK * 32) {
        g_ck[threadIdx.x] = 0u;
    }
}

__global__ void k_prep_emb(const float* __restrict__ emb,
                           __nv_bfloat16* __restrict__ hi,
                           __nv_bfloat16* __restrict__ lo) {
    size_t i4 = (size_t)blockIdx.x * blockDim.x + threadIdx.x;
    if (i4 < (size_t)PV * PE / 4) {
        float4 v = ((const float4*)emb)[i4];
        __nv_bfloat16 h[4], l[4];
        float f[4] = {v.x, v.y, v.z, v.w};
#pragma unroll
        for (int j = 0; j < 4; j++) {
            h[j] = __float2bfloat16_rn(f[j]);
            l[j] = __float2bfloat16_rn(f[j] - __bfloat162float(h[j]));
        }
        ((uint2*)hi)[i4] = *(uint2*)h;
        ((uint2*)lo)[i4] = *(uint2*)l;
    }
}

__global__ void k_prep_winT(const float* __restrict__ Win,
                            __nv_bfloat16* __restrict__ hi,
                            __nv_bfloat16* __restrict__ lo) {
    int idx = blockIdx.x * blockDim.x + threadIdx.x;
    if (idx < PE * PC3) {
        int k = idx / PC3, n = idx - k * PC3;
        float w = Win[idx];
        __nv_bfloat16 h = __float2bfloat16_rn(w);
        hi[(size_t)n * PE + k] = h;
        lo[(size_t)n * PE + k] = __float2bfloat16_rn(w - __bfloat162float(h));
    }
}

// ---------------------------------------------------------------------------
// Kernel 1: xp = emb[x] @ W_in + b_in on mma.sync bf16 (unchanged, ~850us)
// ---------------------------------------------------------------------------
__global__ __launch_bounds__(256) void k_inproj_mma(
    const int* __restrict__ x,
    const __nv_bfloat16* __restrict__ embH,
    const __nv_bfloat16* __restrict__ embL,
    const __nv_bfloat16* __restrict__ winH,
    const __nv_bfloat16* __restrict__ winL,
    const float* __restrict__ bin,
    float* __restrict__ xp)
{
    extern __shared__ char sm2[];
    __shared__ int rowIdx[128];
    const uint32_t smb = smem_u32(sm2);
    const int tid  = threadIdx.x;
    const int warp = tid >> 5;
    const int lane = tid & 31;
    const int wm = warp & 1;
    const int wn = warp >> 1;
    const int m0 = blockIdx.y * 128;
    const int n0 = blockIdx.x * 128;

    if (tid < 128) {
        int m = m0 + tid;
        rowIdx[tid] = x[(size_t)(m & 63) * PT + (m >> 6)];
    }
    __syncthreads();

    float acc[4][4][4];
#pragma unroll
    for (int i = 0; i < 4; i++)
#pragma unroll
        for (int j = 0; j < 4; j++)
#pragma unroll
            for (int r = 0; r < 4; r++) acc[i][j][r] = 0.f;

    float2 bv[4];
#pragma unroll
    for (int nt = 0; nt < 4; nt++) {
        int ng = n0 + wn * 32 + nt * 8 + (lane & 3) * 2;
        bv[nt] = *(const float2*)(bin + ng);
    }

    auto stage = [&](int buf, int c) {
        uint32_t base = smb + buf * IP_BUF;
        int kt0 = c * 32;
#pragma unroll
        for (int i = 0; i < 2; i++) {
            int fl = tid + i * 256;
            int m = fl >> 2, kq = fl & 3;
            const __nv_bfloat16* sh = embH + (size_t)rowIdx[m] * PE + kt0 + kq * 8;
            const __nv_bfloat16* sl = embL + (size_t)rowIdx[m] * PE + kt0 + kq * 8;
            cp16(base + m * IPROW + kq * 16, sh);
            cp16(base + 10240 + m * IPROW + kq * 16, sl);
            const __nv_bfloat16* bh = winH + (size_t)(n0 + m) * PE + kt0 + kq * 8;
            const __nv_bfloat16* bl = winL + (size_t)(n0 + m) * PE + kt0 + kq * 8;
            cp16(base + 20480 + m * IPROW + kq * 16, bh);
            cp16(base + 30720 + m * IPROW + kq * 16, bl);
        }
    };

    stage(0, 0); cp_commit();
#pragma unroll 1
    for (int c = 0; c < 8; c++) {
        cp_wait0();
        __syncthreads();
        if (c < 7) { stage((c + 1) & 1, c + 1); cp_commit(); }
        uint32_t base = smb + (c & 1) * IP_BUF;
#pragma unroll
        for (int kt = 0; kt < 2; kt++) {
            uint32_t bh[4][2], bl[4][2];
#pragma unroll
            for (int nt = 0; nt < 4; nt++) {
                uint32_t a = base + 20480 +
                    (uint32_t)((wn * 32 + nt * 8 + (lane >> 2)) * IPROW + kt * 32 + (lane & 3) * 4);
                asm volatile("ld.shared.b32 %0, [%1];" : "=r"(bh[nt][0]) : "r"(a));
                asm volatile("ld.shared.b32 %0, [%1];" : "=r"(bh[nt][1]) : "r"(a + 16));
                asm volatile("ld.shared.b32 %0, [%1];" : "=r"(bl[nt][0]) : "r"(a + 10240));
                asm volatile("ld.shared.b32 %0, [%1];" : "=r"(bl[nt][1]) : "r"(a + 10240 + 16));
            }
            uint32_t ah[4][4], al[4][4];
#pragma unroll
            for (int mt = 0; mt < 4; mt++) {
                uint32_t a = base +
                    (uint32_t)((wm * 64 + mt * 16 + (lane & 15)) * IPROW + (lane >> 4) * 16 + kt * 32);
                ldsm_x4(ah[mt], a);
                ldsm_x4(al[mt], a + 10240);
            }
#pragma unroll
            for (int mt = 0; mt < 4; mt++)
#pragma unroll
                for (int nt = 0; nt < 4; nt++) mma_bf16(acc[mt][nt], ah[mt], bh[nt]);
#pragma unroll
            for (int mt = 0; mt < 4; mt++)
#pragma unroll
                for (int nt = 0; nt < 4; nt++) mma_bf16(acc[mt][nt], ah[mt], bl[nt]);
#pragma unroll
            for (int mt = 0; mt < 4; mt++)
#pragma unroll
                for (int nt = 0; nt < 4; nt++) mma_bf16(acc[mt][nt], al[mt], bh[nt]);
        }
    }

#pragma unroll
    for (int mt = 0; mt < 4; mt++) {
        int mg = m0 + wm * 64 + mt * 16 + (lane >> 2);
#pragma unroll
        for (int nt = 0; nt < 4; nt++) {
            int ng = n0 + wn * 32 + nt * 8 + (lane & 3) * 2;
            *(float2*)(xp + (size_t)mg * PC3 + ng) =
                make_float2(acc[mt][nt][0] + bv[nt].x, acc[mt][nt][1] + bv[nt].y);
            *(float2*)(xp + (size_t)(mg + 8) * PC3 + ng) =
                make_float2(acc[mt][nt][2] + bv[nt].x, acc[mt][nt][3] + bv[nt].y);
        }
    }
}

// ---------------------------------------------------------------------------
// stage one 256-k chunk of A = [h_hi(64); h_lo(64)], LDG batched 8-deep
// ---------------------------------------------------------------------------
__device__ __forceinline__ void stage_chunk(char* Abuf,
                                            const __nv_bfloat16* __restrict__ sHi,
                                            const __nv_bfloat16* __restrict__ sLo,
                                            int kc, int tid)
{
#pragma unroll
    for (int h = 0; h < 2; h++) {
        uint4 v[8];
#pragma unroll
        for (int i = 0; i < 8; i++) {
            int fl = tid + (h * 8 + i) * TPB;
            int m  = fl >> 5;
            int kq = fl & 31;
            const __nv_bfloat16* p = (m < 64)
                ? (sHi + (size_t)m * PU + kc + kq * 8)
                : (sLo + (size_t)(m - 64) * PU + kc + kq * 8);
            v[i] = *(const uint4*)p;
        }
#pragma unroll
        for (int i = 0; i < 8; i++) {
            int fl = tid + (h * 8 + i) * TPB;
            int m  = fl >> 5;
            int kq = fl & 31;
            *(uint4*)(Abuf + m * AROWB + kq * 16) = v[i];
        }
    }
}

// ---------------------------------------------------------------------------
// Kernel 2: persistent GRU scan (R9 structure; chunk-granular dataflow sync)
// ---------------------------------------------------------------------------
__global__ __launch_bounds__(TPB, 1) void k_gru(
    const float* __restrict__ xp,
    const float* __restrict__ h0,
    const float* __restrict__ Wrec,
    const float* __restrict__ brec,
    float* __restrict__ out,
    float* __restrict__ hlast)
{
    extern __shared__ char sm[];
    const uint32_t smb = smem_u32(sm);
    const int tid   = threadIdx.x;
    const int warp  = tid >> 5;
    const int lane  = tid & 31;
    const int ubase = blockIdx.x * TILE_U;
    const int myck  = blockIdx.x >> 5;     // k-chunk containing this block's u

    __nv_bfloat16* WloS = (__nv_bfloat16*)(sm + SM_WLO);
    float* os  = (float*)(sm + SM_OS);
    uint32_t* osh = (uint32_t*)(sm + SM_OSH);
    uint32_t* osl = (uint32_t*)(sm + SM_OSL);
    float* brs = (float*)(sm + SM_BRS);
    float* Dp  = (float*)sm;

    // Whi register fragments: warp's 8 ktiles = c*16 + warp*2 + j
    uint32_t Bh[8][3][2];
#pragma unroll
    for (int c = 0; c < 4; c++)
#pragma unroll
        for (int j = 0; j < 2; j++) {
            int KT = c * 16 + warp * 2 + j;
            int k0 = KT * 16 + (lane & 3) * 2;
#pragma unroll
            for (int nt = 0; nt < 3; nt++) {
                int n = nt * 8 + (lane >> 2);
                int col = (n >> 3) * PU + ubase + (n & 7);
                float w0 = Wrec[(size_t)k0 * PC3 + col];
                float w1 = Wrec[(size_t)(k0 + 1) * PC3 + col];
                float w8 = Wrec[(size_t)(k0 + 8) * PC3 + col];
                float w9 = Wrec[(size_t)(k0 + 9) * PC3 + col];
                Bh[c * 2 + j][nt][0] = pack_bf16x2(__bfloat162float(__float2bfloat16_rn(w0)),
                                                   __bfloat162float(__float2bfloat16_rn(w1)));
                Bh[c * 2 + j][nt][1] = pack_bf16x2(__bfloat162float(__float2bfloat16_rn(w8)),
                                                   __bfloat162float(__float2bfloat16_rn(w9)));
            }
        }
    for (int idx = tid; idx < NCOL * PU; idx += TPB) {
        int n = idx >> 10, k = idx & 1023;
        int col = (n >> 3) * PU + ubase + (n & 7);
        float w = Wrec[(size_t)k * PC3 + col];
        float whi = __bfloat162float(__float2bfloat16_rn(w));
        WloS[n * WLOST + k] = __float2bfloat16_rn(w - whi);
    }
    if (tid < NCOL) brs[tid] = brec[(tid >> 3) * PU + ubase + (tid & 7)];
    __syncthreads();

    const int eb = tid >> 2;         // epilogue batch 0..63
    const int uo = tid & 3;          // u-pair 0..3
    const uint32_t laneoff = (uint32_t)((lane & 15) * AROWB + (lane >> 4) * 16);

    // prologue prefetch for t=0
    float2 xz, xr, xh, hp;
    {
        const float* xrow = xp + (size_t)eb * PC3 + ubase + uo * 2;
        xz = *(const float2*)(xrow);
        xr = *(const float2*)(xrow + PU);
        xh = *(const float2*)(xrow + 2 * PU);
        hp = *(const float2*)(h0 + (size_t)eb * PU + ubase + uo * 2);
    }

    for (int t = 0; t < PT; t++) {
        const int par = t & 1;
        const __nv_bfloat16* sHi = g_hhi[par];
        const __nv_bfloat16* sLo = g_hlo[par];
        __nv_bfloat16* dHi = g_hhi[par ^ 1];
        __nv_bfloat16* dLo = g_hlo[par ^ 1];
        const unsigned tgt = (unsigned)(32 * t);

        float acc[8][3][4];
#pragma unroll
        for (int mt = 0; mt < 8; mt++)
#pragma unroll
            for (int nt = 0; nt < 3; nt++)
#pragma unroll
                for (int r = 0; r < 4; r++) acc[mt][nt][r] = 0.f;

        wait_chunk(0, tgt);
        stage_chunk(sm, sHi, sLo, 0, tid);
        __syncthreads();

#pragma unroll 1
        for (int c = 0; c < NCHNK; c++) {
            const uint32_t abase = smb + (uint32_t)((c & 1) * ABUFB);
#pragma unroll
            for (int j = 0; j < 2; j++) {
                const int ktl = warp * 2 + j;
                const int KT  = c * 16 + ktl;
                uint32_t bl[3][2];
#pragma unroll
                for (int nt = 0; nt < 3; nt++) {
                    int n = nt * 8 + (lane >> 2);
                    const __nv_bfloat16* wl = WloS + n * WLOST + KT * 16 + (lane & 3) * 2;
                    bl[nt][0] = *(const uint32_t*)(wl);
                    bl[nt][1] = *(const uint32_t*)(wl + 8);
                }
#pragma unroll
                for (int mt = 0; mt < 8; mt++) {
                    uint32_t a[4];
                    ldsm_x4(a, abase + (uint32_t)(mt * 16 * AROWB + ktl * 32) + laneoff);
#pragma unroll
                    for (int nt = 0; nt < 3; nt++) mma_bf16(acc[mt][nt], a, Bh[c * 2 + j][nt]);
                    if (mt < 4) {
#pragma unroll
                        for (int nt = 0; nt < 3; nt++) mma_bf16(acc[mt][nt], a, bl[nt]);
                    }
                }
            }
            if (c < NCHNK - 1) {
                wait_chunk(c + 1, tgt);
                stage_chunk(sm + ((c + 1) & 1) * ABUFB, sHi, sLo, (c + 1) * KCHUNK, tid);
            }
            __syncthreads();
        }

        // ---- k-partials to smem (overlay A; all MMA reads done) ----
#pragma unroll
        for (int mt = 0; mt < 8; mt++)
#pragma unroll
            for (int nt = 0; nt < 3; nt++) {
                int m = mt * 16 + (lane >> 2);
                int n = nt * 8 + (lane & 3) * 2;
                *(float2*)&Dp[((warp << 7) + m) * DPST + n] =
                    make_float2(acc[mt][nt][0], acc[mt][nt][1]);
                *(float2*)&Dp[((warp << 7) + m + 8) * DPST + n] =
                    make_float2(acc[mt][nt][2], acc[mt][nt][3]);
            }
        __syncthreads();

        // ---- reduce + gates ----
        {
            float s0 = 0.f, s1 = 0.f, s2 = 0.f, s3 = 0.f, s4 = 0.f, s5 = 0.f;
#pragma unroll
            for (int w = 0; w < 8; w++) {
#pragma unroll
                for (int rr = 0; rr < 2; rr++) {
                    const float* base = Dp + ((w << 7) + eb + rr * 64) * DPST + uo * 2;
                    float2 vz = *(const float2*)(base);
                    float2 vr = *(const float2*)(base + 8);
                    float2 vh = *(const float2*)(base + 16);
                    s0 += vz.x; s1 += vz.y;
                    s2 += vr.x; s3 += vr.y;
                    s4 += vh.x; s5 += vh.y;
                }
            }
            int u0 = uo * 2;
            float z0 = sig_fast(xz.x + s0 + brs[u0]);
            float r0 = sig_fast(xr.x + s2 + brs[8 + u0]);
            float c0 = tanh_fast(xh.x + r0 * (s4 + brs[16 + u0]));
            float hn0 = z0 * hp.x + (1.f - z0) * c0;
            float z1 = sig_fast(xz.y + s1 + brs[u0 + 1]);
            float r1 = sig_fast(xr.y + s3 + brs[8 + u0 + 1]);
            float c1 = tanh_fast(xh.y + r1 * (s5 + brs[16 + u0 + 1]));
            float hn1 = z1 * hp.y + (1.f - z1) * c1;

            *(float2*)&os[eb * 8 + u0] = make_float2(hn0, hn1);
            __nv_bfloat16 h0b = __float2bfloat16_rn(hn0);
            __nv_bfloat16 h1b = __float2bfloat16_rn(hn1);
            osh[eb * 4 + uo] = pack_bf16x2(__bfloat162float(h0b), __bfloat162float(h1b));
            osl[eb * 4 + uo] = pack_bf16x2(hn0 - __bfloat162float(h0b),
                                           hn1 - __bfloat162float(h1b));
        }
        __syncthreads();

        // ---- publish next-step h splits (cross-block critical path) ----
        if (tid < 128) {
            int bb = tid >> 1, hf = tid & 1;
            uint2 vh = *(const uint2*)&osh[bb * 4 + hf * 2];
            uint2 vl = *(const uint2*)&osl[bb * 4 + hf * 2];
            *(uint2*)(dHi + (size_t)bb * PU + ubase + hf * 4) = vh;
            *(uint2*)(dLo + (size_t)bb * PU + ubase + hf * 4) = vl;
        }
        __syncthreads();

        // ---- signal: this block's u-slice for step t+1 is published ----
        if (tid == 0) {
            __threadfence();
            atomicAdd(&g_ck[myck * 32], 1u);
        }

        // ---- off critical path: out store + next-step epilogue prefetch ----
        if (tid < 128) {
            int bb = tid >> 1, hf = tid & 1;
            float4 v = *(const float4*)&os[bb * 8 + hf * 4];
            *(float4*)(out + ((size_t)bb * PT + t) * PU + ubase + hf * 4) = v;
            if (t == PT - 1 && hlast != nullptr)
                *(float4*)(hlast + (size_t)bb * PU + ubase + hf * 4) = v;
        }
        if (t < PT - 1) {
            const float* xrow = xp + ((size_t)(t + 1) * PB + eb) * PC3 + ubase + uo * 2;
            xz = *(const float2*)(xrow);
            xr = *(const float2*)(xrow + PU);
            xh = *(const float2*)(xrow + 2 * PU);
            hp = *(const float2*)&os[eb * 8 + uo * 2];
        }
    }
}

// ---------------------------------------------------------------------------
// launch
// ---------------------------------------------------------------------------
extern "C" void kernel_launch(void* const* d_in, const int* in_sizes, int n_in,
                              void* d_out, int out_size)
{
    const int*   x       = (const int*)  d_in[0];
    const float* initial = (const float*)d_in[1];
    const float* emb     = (const float*)d_in[2];
    const float* Win     = (const float*)d_in[3];
    const float* Wrec    = (const float*)d_in[4];
    const float* bin     = (const float*)d_in[5];
    const float* brec    = (const float*)d_in[6];

    float* out = (float*)d_out;
    float* hlast = nullptr;
    const long long n_outputs = (long long)PB * PT * PU;
    if ((long long)out_size >= n_outputs + (long long)PB * PU) {
        hlast = out + (size_t)n_outputs;
    }

    float* xp = nullptr;
    cudaGetSymbolAddress((void**)&xp, g_xp);
    __nv_bfloat16 *hhi, *hlo, *embh, *embl, *winth, *wintl;
    cudaGetSymbolAddress((void**)&hhi, g_hhi);
    cudaGetSymbolAddress((void**)&hlo, g_hlo);
    cudaGetSymbolAddress((void**)&embh, g_embh);
    cudaGetSymbolAddress((void**)&embl, g_embl);
    cudaGetSymbolAddress((void**)&winth, g_winth);
    cudaGetSymbolAddress((void**)&wintl, g_wintl);

    // prep: splits + transpose + counter reset (in k_split_init)
    k_split_init<<<(PB * PU + 255) / 256, 256>>>(initial, hhi, hlo);
    k_prep_emb<<<(int)(((size_t)PV * PE / 4 + 255) / 256), 256>>>(emb, embh, embl);
    k_prep_winT<<<(PE * PC3 + 255) / 256, 256>>>(Win, winth, wintl);

    // GEMM1 on tensor cores
    cudaFuncSetAttribute(k_inproj_mma, cudaFuncAttributeMaxDynamicSharedMemorySize, IP_TOTAL);
    dim3 g1(PC3 / 128, (PT * PB) / 128);
    k_inproj_mma<<<g1, 256, IP_TOTAL>>>(x, embh, embl, winth, wintl, bin, xp);

    // persistent GRU scan (dataflow-synced)
    cudaFuncSetAttribute(k_gru, cudaFuncAttributeMaxDynamicSharedMemorySize, SM_TOTAL);
    k_gru<<<NBLK, TPB, SM_TOTAL>>>(xp, initial, Wrec, brec, out, hlast);
}

// round 16
// speedup vs baseline: 1.2239x; 1.2239x over previous
#include <cuda_runtime.h>
#include <cuda_bf16.h>
#include <math.h>
#include <stdint.h>

// Problem dims
#define PB 64
#define PT 1024
#define PE 256
#define PU 1024
#define PC3 3072
#define PV 32000

#define NBLK 128
#define TILE_U 8          // u per block; N = 24 cols (3 gates x 8 u)
#define TPB 256           // 8 warps
#define NCOL 24
#define KCHUNK 256        // k per staged A chunk (scan)
#define NCHNK (PU / KCHUNK)
#define AROWB 528         // scan A smem row stride bytes
#define ABUFB (128 * AROWB)
#define WLOST 1032        // Wlo smem row stride (bf16 elems)
#define DPST 26           // Dp row stride (floats), conflict-reduced

// scan smem byte offsets
#define SM_A     0
#define SM_WLO   (2 * ABUFB)             // 135168
#define SM_OS    184704
#define SM_OSH   186752
#define SM_OSL   187776
#define SM_BRS   188800
#define SM_TOTAL 188928
// Dp overlays A buffers: 512 * DPST * 4 = 53248 <= 135168 (hi/lo folded)

// inproj-mma smem
#define IP_BUF   40960
#define IP_TOTAL (2 * IP_BUF)
#define IPROW 80

// ---------------------------------------------------------------------------
// global scratch
// ---------------------------------------------------------------------------
__device__ float g_xp[(size_t)PT * PB * PC3];
__device__ __nv_bfloat16 g_hhi[2][PB * PU];
__device__ __nv_bfloat16 g_hlo[2][PB * PU];
__device__ __nv_bfloat16 g_embh[(size_t)PV * PE];
__device__ __nv_bfloat16 g_embl[(size_t)PV * PE];
__device__ __nv_bfloat16 g_winth[(size_t)PC3 * PE];
__device__ __nv_bfloat16 g_wintl[(size_t)PC3 * PE];

// flat grid barrier (R9-proven; relative snapshot -> replay-safe)
__device__ unsigned g_bar_count = 0;
__device__ unsigned g_bar_gen = 0;

// ---------------------------------------------------------------------------
// PTX wrappers (baseline PTX, valid on compute_103)
// ---------------------------------------------------------------------------
__device__ __forceinline__ uint32_t smem_u32(const void* p) {
    uint32_t a;
    asm("{ .reg .u64 t; cvta.to.shared.u64 t, %1; cvt.u32.u64 %0, t; }" : "=r"(a) : "l"(p));
    return a;
}
__device__ __forceinline__ void mma_bf16(float* d, const uint32_t* a, const uint32_t* b) {
    asm volatile(
        "mma.sync.aligned.m16n8k16.row.col.f32.bf16.bf16.f32 "
        "{%0,%1,%2,%3}, {%4,%5,%6,%7}, {%8,%9}, {%0,%1,%2,%3};"
        : "+f"(d[0]), "+f"(d[1]), "+f"(d[2]), "+f"(d[3])
        : "r"(a[0]), "r"(a[1]), "r"(a[2]), "r"(a[3]), "r"(b[0]), "r"(b[1]));
}
__device__ __forceinline__ void ldsm_x4(uint32_t* r, uint32_t addr) {
    asm volatile("ldmatrix.sync.aligned.m8n8.x4.shared.b16 {%0,%1,%2,%3}, [%4];"
                 : "=r"(r[0]), "=r"(r[1]), "=r"(r[2]), "=r"(r[3]) : "r"(addr));
}
__device__ __forceinline__ void cp16(uint32_t dst, const void* src) {
    asm volatile("cp.async.cg.shared.global [%0], [%1], 16;" :: "r"(dst), "l"(src));
}
__device__ __forceinline__ void cp_commit() { asm volatile("cp.async.commit_group;" ::: "memory"); }
__device__ __forceinline__ void cp_wait0()  { asm volatile("cp.async.wait_group 0;" ::: "memory"); }
__device__ __forceinline__ uint32_t pack_bf16x2(float lo, float hi) {
    __nv_bfloat162 v = __floats2bfloat162_rn(lo, hi);
    return *(uint32_t*)&v;
}
__device__ __forceinline__ float sig_fast(float v) {
    return 1.0f / (1.0f + __expf(-v));
}
__device__ __forceinline__ float tanh_fast(float v) {
    float ax = fabsf(v);
    float e  = __expf(2.0f * ax);
    float t  = 1.0f - 2.0f / (e + 1.0f);
    return copysignf(t, v);
}

// ---------------------------------------------------------------------------
// prep kernels
// ---------------------------------------------------------------------------
__global__ void k_split_init(const float* __restrict__ h0,
                             __nv_bfloat16* __restrict__ hi,
                             __nv_bfloat16* __restrict__ lo) {
    int idx = blockIdx.x * blockDim.x + threadIdx.x;
    if (idx < PB * PU) {
        float v = h0[idx];
        __nv_bfloat16 h = __float2bfloat16_rn(v);
        hi[idx] = h;
        lo[idx] = __float2bfloat16_rn(v - __bfloat162float(h));
    }
}

__global__ void k_prep_emb(const float* __restrict__ emb,
                           __nv_bfloat16* __restrict__ hi,
                           __nv_bfloat16* __restrict__ lo) {
    size_t i4 = (size_t)blockIdx.x * blockDim.x + threadIdx.x;
    if (i4 < (size_t)PV * PE / 4) {
        float4 v = ((const float4*)emb)[i4];
        __nv_bfloat16 h[4], l[4];
        float f[4] = {v.x, v.y, v.z, v.w};
#pragma unroll
        for (int j = 0; j < 4; j++) {
            h[j] = __float2bfloat16_rn(f[j]);
            l[j] = __float2bfloat16_rn(f[j] - __bfloat162float(h[j]));
        }
        ((uint2*)hi)[i4] = *(uint2*)h;
        ((uint2*)lo)[i4] = *(uint2*)l;
    }
}

__global__ void k_prep_winT(const float* __restrict__ Win,
                            __nv_bfloat16* __restrict__ hi,
                            __nv_bfloat16* __restrict__ lo) {
    int idx = blockIdx.x * blockDim.x + threadIdx.x;
    if (idx < PE * PC3) {
        int k = idx / PC3, n = idx - k * PC3;
        float w = Win[idx];
        __nv_bfloat16 h = __float2bfloat16_rn(w);
        hi[(size_t)n * PE + k] = h;
        lo[(size_t)n * PE + k] = __float2bfloat16_rn(w - __bfloat162float(h));
    }
}

// ---------------------------------------------------------------------------
// Kernel 1: xp = emb[x] @ W_in + b_in on mma.sync bf16 (unchanged, ~850us)
// ---------------------------------------------------------------------------
__global__ __launch_bounds__(256) void k_inproj_mma(
    const int* __restrict__ x,
    const __nv_bfloat16* __restrict__ embH,
    const __nv_bfloat16* __restrict__ embL,
    const __nv_bfloat16* __restrict__ winH,
    const __nv_bfloat16* __restrict__ winL,
    const float* __restrict__ bin,
    float* __restrict__ xp)
{
    extern __shared__ char sm2[];
    __shared__ int rowIdx[128];
    const uint32_t smb = smem_u32(sm2);
    const int tid  = threadIdx.x;
    const int warp = tid >> 5;
    const int lane = tid & 31;
    const int wm = warp & 1;
    const int wn = warp >> 1;
    const int m0 = blockIdx.y * 128;
    const int n0 = blockIdx.x * 128;

    if (tid < 128) {
        int m = m0 + tid;
        rowIdx[tid] = x[(size_t)(m & 63) * PT + (m >> 6)];
    }
    __syncthreads();

    float acc[4][4][4];
#pragma unroll
    for (int i = 0; i < 4; i++)
#pragma unroll
        for (int j = 0; j < 4; j++)
#pragma unroll
            for (int r = 0; r < 4; r++) acc[i][j][r] = 0.f;

    float2 bv[4];
#pragma unroll
    for (int nt = 0; nt < 4; nt++) {
        int ng = n0 + wn * 32 + nt * 8 + (lane & 3) * 2;
        bv[nt] = *(const float2*)(bin + ng);
    }

    auto stage = [&](int buf, int c) {
        uint32_t base = smb + buf * IP_BUF;
        int kt0 = c * 32;
#pragma unroll
        for (int i = 0; i < 2; i++) {
            int fl = tid + i * 256;
            int m = fl >> 2, kq = fl & 3;
            const __nv_bfloat16* sh = embH + (size_t)rowIdx[m] * PE + kt0 + kq * 8;
            const __nv_bfloat16* sl = embL + (size_t)rowIdx[m] * PE + kt0 + kq * 8;
            cp16(base + m * IPROW + kq * 16, sh);
            cp16(base + 10240 + m * IPROW + kq * 16, sl);
            const __nv_bfloat16* bh = winH + (size_t)(n0 + m) * PE + kt0 + kq * 8;
            const __nv_bfloat16* bl = winL + (size_t)(n0 + m) * PE + kt0 + kq * 8;
            cp16(base + 20480 + m * IPROW + kq * 16, bh);
            cp16(base + 30720 + m * IPROW + kq * 16, bl);
        }
    };

    stage(0, 0); cp_commit();
#pragma unroll 1
    for (int c = 0; c < 8; c++) {
        cp_wait0();
        __syncthreads();
        if (c < 7) { stage((c + 1) & 1, c + 1); cp_commit(); }
        uint32_t base = smb + (c & 1) * IP_BUF;
#pragma unroll
        for (int kt = 0; kt < 2; kt++) {
            uint32_t bh[4][2], bl[4][2];
#pragma unroll
            for (int nt = 0; nt < 4; nt++) {
                uint32_t a = base + 20480 +
                    (uint32_t)((wn * 32 + nt * 8 + (lane >> 2)) * IPROW + kt * 32 + (lane & 3) * 4);
                asm volatile("ld.shared.b32 %0, [%1];" : "=r"(bh[nt][0]) : "r"(a));
                asm volatile("ld.shared.b32 %0, [%1];" : "=r"(bh[nt][1]) : "r"(a + 16));
                asm volatile("ld.shared.b32 %0, [%1];" : "=r"(bl[nt][0]) : "r"(a + 10240));
                asm volatile("ld.shared.b32 %0, [%1];" : "=r"(bl[nt][1]) : "r"(a + 10240 + 16));
            }
            uint32_t ah[4][4], al[4][4];
#pragma unroll
            for (int mt = 0; mt < 4; mt++) {
                uint32_t a = base +
                    (uint32_t)((wm * 64 + mt * 16 + (lane & 15)) * IPROW + (lane >> 4) * 16 + kt * 32);
                ldsm_x4(ah[mt], a);
                ldsm_x4(al[mt], a + 10240);
            }
#pragma unroll
            for (int mt = 0; mt < 4; mt++)
#pragma unroll
                for (int nt = 0; nt < 4; nt++) mma_bf16(acc[mt][nt], ah[mt], bh[nt]);
#pragma unroll
            for (int mt = 0; mt < 4; mt++)
#pragma unroll
                for (int nt = 0; nt < 4; nt++) mma_bf16(acc[mt][nt], ah[mt], bl[nt]);
#pragma unroll
            for (int mt = 0; mt < 4; mt++)
#pragma unroll
                for (int nt = 0; nt < 4; nt++) mma_bf16(acc[mt][nt], al[mt], bh[nt]);
        }
    }

#pragma unroll
    for (int mt = 0; mt < 4; mt++) {
        int mg = m0 + wm * 64 + mt * 16 + (lane >> 2);
#pragma unroll
        for (int nt = 0; nt < 4; nt++) {
            int ng = n0 + wn * 32 + nt * 8 + (lane & 3) * 2;
            *(float2*)(xp + (size_t)mg * PC3 + ng) =
                make_float2(acc[mt][nt][0] + bv[nt].x, acc[mt][nt][1] + bv[nt].y);
            *(float2*)(xp + (size_t)(mg + 8) * PC3 + ng) =
                make_float2(acc[mt][nt][2] + bv[nt].x, acc[mt][nt][3] + bv[nt].y);
        }
    }
}

// ---------------------------------------------------------------------------
// stage one 256-k chunk of A = [h_hi(64); h_lo(64)], LDG batched 8-deep
// ---------------------------------------------------------------------------
__device__ __forceinline__ void stage_chunk(char* Abuf,
                                            const __nv_bfloat16* __restrict__ sHi,
                                            const __nv_bfloat16* __restrict__ sLo,
                                            int kc, int tid)
{
#pragma unroll
    for (int h = 0; h < 2; h++) {
        uint4 v[8];
#pragma unroll
        for (int i = 0; i < 8; i++) {
            int fl = tid + (h * 8 + i) * TPB;
            int m  = fl >> 5;
            int kq = fl & 31;
            const __nv_bfloat16* p = (m < 64)
                ? (sHi + (size_t)m * PU + kc + kq * 8)
                : (sLo + (size_t)(m - 64) * PU + kc + kq * 8);
            v[i] = *(const uint4*)p;
        }
#pragma unroll
        for (int i = 0; i < 8; i++) {
            int fl = tid + (h * 8 + i) * TPB;
            int m  = fl >> 5;
            int kq = fl & 31;
            *(uint4*)(Abuf + m * AROWB + kq * 16) = v[i];
        }
    }
}

// ---------------------------------------------------------------------------
// Kernel 2: persistent GRU scan (R9 structure + in-register hi/lo fold)
// ---------------------------------------------------------------------------
__global__ __launch_bounds__(TPB, 1) void k_gru(
    const float* __restrict__ xp,
    const float* __restrict__ h0,
    const float* __restrict__ Wrec,
    const float* __restrict__ brec,
    float* __restrict__ out,
    float* __restrict__ hlast)
{
    extern __shared__ char sm[];
    const uint32_t smb = smem_u32(sm);
    const int tid   = threadIdx.x;
    const int warp  = tid >> 5;
    const int lane  = tid & 31;
    const int ubase = blockIdx.x * TILE_U;

    __nv_bfloat16* WloS = (__nv_bfloat16*)(sm + SM_WLO);
    float* os  = (float*)(sm + SM_OS);
    uint32_t* osh = (uint32_t*)(sm + SM_OSH);
    uint32_t* osl = (uint32_t*)(sm + SM_OSL);
    float* brs = (float*)(sm + SM_BRS);
    float* Dp  = (float*)sm;

    // Whi register fragments: warp's 8 ktiles = c*16 + warp*2 + j
    uint32_t Bh[8][3][2];
#pragma unroll
    for (int c = 0; c < 4; c++)
#pragma unroll
        for (int j = 0; j < 2; j++) {
            int KT = c * 16 + warp * 2 + j;
            int k0 = KT * 16 + (lane & 3) * 2;
#pragma unroll
            for (int nt = 0; nt < 3; nt++) {
                int n = nt * 8 + (lane >> 2);
                int col = (n >> 3) * PU + ubase + (n & 7);
                float w0 = Wrec[(size_t)k0 * PC3 + col];
                float w1 = Wrec[(size_t)(k0 + 1) * PC3 + col];
                float w8 = Wrec[(size_t)(k0 + 8) * PC3 + col];
                float w9 = Wrec[(size_t)(k0 + 9) * PC3 + col];
                Bh[c * 2 + j][nt][0] = pack_bf16x2(__bfloat162float(__float2bfloat16_rn(w0)),
                                                   __bfloat162float(__float2bfloat16_rn(w1)));
                Bh[c * 2 + j][nt][1] = pack_bf16x2(__bfloat162float(__float2bfloat16_rn(w8)),
                                                   __bfloat162float(__float2bfloat16_rn(w9)));
            }
        }
    for (int idx = tid; idx < NCOL * PU; idx += TPB) {
        int n = idx >> 10, k = idx & 1023;
        int col = (n >> 3) * PU + ubase + (n & 7);
        float w = Wrec[(size_t)k * PC3 + col];
        float whi = __bfloat162float(__float2bfloat16_rn(w));
        WloS[n * WLOST + k] = __float2bfloat16_rn(w - whi);
    }
    if (tid < NCOL) brs[tid] = brec[(tid >> 3) * PU + ubase + (tid & 7)];
    __syncthreads();

    const int eb = tid >> 2;         // epilogue batch 0..63
    const int uo = tid & 3;          // u-pair 0..3
    const uint32_t laneoff = (uint32_t)((lane & 15) * AROWB + (lane >> 4) * 16);

    // prologue prefetch for t=0
    float2 xz, xr, xh, hp;
    {
        const float* xrow = xp + (size_t)eb * PC3 + ubase + uo * 2;
        xz = *(const float2*)(xrow);
        xr = *(const float2*)(xrow + PU);
        xh = *(const float2*)(xrow + 2 * PU);
        hp = *(const float2*)(h0 + (size_t)eb * PU + ubase + uo * 2);
    }

    for (int t = 0; t < PT; t++) {
        const int par = t & 1;
        const __nv_bfloat16* sHi = g_hhi[par];
        const __nv_bfloat16* sLo = g_hlo[par];
        __nv_bfloat16* dHi = g_hhi[par ^ 1];
        __nv_bfloat16* dLo = g_hlo[par ^ 1];

        float acc[8][3][4];
#pragma unroll
        for (int mt = 0; mt < 8; mt++)
#pragma unroll
            for (int nt = 0; nt < 3; nt++)
#pragma unroll
                for (int r = 0; r < 4; r++) acc[mt][nt][r] = 0.f;

        stage_chunk(sm, sHi, sLo, 0, tid);
        __syncthreads();

#pragma unroll 1
        for (int c = 0; c < NCHNK; c++) {
            const uint32_t abase = smb + (uint32_t)((c & 1) * ABUFB);
#pragma unroll
            for (int j = 0; j < 2; j++) {
                const int ktl = warp * 2 + j;
                const int KT  = c * 16 + ktl;
                uint32_t bl[3][2];
#pragma unroll
                for (int nt = 0; nt < 3; nt++) {
                    int n = nt * 8 + (lane >> 2);
                    const __nv_bfloat16* wl = WloS + n * WLOST + KT * 16 + (lane & 3) * 2;
                    bl[nt][0] = *(const uint32_t*)(wl);
                    bl[nt][1] = *(const uint32_t*)(wl + 8);
                }
#pragma unroll
                for (int mt = 0; mt < 8; mt++) {
                    uint32_t a[4];
                    ldsm_x4(a, abase + (uint32_t)(mt * 16 * AROWB + ktl * 32) + laneoff);
#pragma unroll
                    for (int nt = 0; nt < 3; nt++) mma_bf16(acc[mt][nt], a, Bh[c * 2 + j][nt]);
                    if (mt < 4) {
#pragma unroll
                        for (int nt = 0; nt < 3; nt++) mma_bf16(acc[mt][nt], a, bl[nt]);
                    }
                }
            }
            if (c < NCHNK - 1)
                stage_chunk(sm + ((c + 1) & 1) * ABUFB, sHi, sLo, (c + 1) * KCHUNK, tid);
            __syncthreads();
        }

        // ---- fold hi/lo halves IN REGISTERS (row m and m+64 = same batch b,
        //      same lane layout) then write only 4 folded m-tiles to smem ----
#pragma unroll
        for (int mt = 0; mt < 4; mt++)
#pragma unroll
            for (int nt = 0; nt < 3; nt++)
#pragma unroll
                for (int r = 0; r < 4; r++)
                    acc[mt][nt][r] += acc[mt + 4][nt][r];
#pragma unroll
        for (int mt = 0; mt < 4; mt++)
#pragma unroll
            for (int nt = 0; nt < 3; nt++) {
                int m = mt * 16 + (lane >> 2);
                int n = nt * 8 + (lane & 3) * 2;
                *(float2*)&Dp[((warp << 6) + m) * DPST + n] =
                    make_float2(acc[mt][nt][0], acc[mt][nt][1]);
                *(float2*)&Dp[((warp << 6) + m + 8) * DPST + n] =
                    make_float2(acc[mt][nt][2], acc[mt][nt][3]);
            }
        __syncthreads();

        // ---- reduce (8 warps, halves already folded) + gates ----
        {
            float s0 = 0.f, s1 = 0.f, s2 = 0.f, s3 = 0.f, s4 = 0.f, s5 = 0.f;
#pragma unroll
            for (int w = 0; w < 8; w++) {
                const float* base = Dp + ((w << 6) + eb) * DPST + uo * 2;
                float2 vz = *(const float2*)(base);
                float2 vr = *(const float2*)(base + 8);
                float2 vh = *(const float2*)(base + 16);
                s0 += vz.x; s1 += vz.y;
                s2 += vr.x; s3 += vr.y;
                s4 += vh.x; s5 += vh.y;
            }
            int u0 = uo * 2;
            float z0 = sig_fast(xz.x + s0 + brs[u0]);
            float r0 = sig_fast(xr.x + s2 + brs[8 + u0]);
            float c0 = tanh_fast(xh.x + r0 * (s4 + brs[16 + u0]));
            float hn0 = z0 * hp.x + (1.f - z0) * c0;
            float z1 = sig_fast(xz.y + s1 + brs[u0 + 1]);
            float r1 = sig_fast(xr.y + s3 + brs[8 + u0 + 1]);
            float c1 = tanh_fast(xh.y + r1 * (s5 + brs[16 + u0 + 1]));
            float hn1 = z1 * hp.y + (1.f - z1) * c1;

            *(float2*)&os[eb * 8 + u0] = make_float2(hn0, hn1);
            __nv_bfloat16 h0b = __float2bfloat16_rn(hn0);
            __nv_bfloat16 h1b = __float2bfloat16_rn(hn1);
            osh[eb * 4 + uo] = pack_bf16x2(__bfloat162float(h0b), __bfloat162float(h1b));
            osl[eb * 4 + uo] = pack_bf16x2(hn0 - __bfloat162float(h0b),
                                           hn1 - __bfloat162float(h1b));
        }
        __syncthreads();

        // ---- publish next-step h splits (cross-block critical path) ----
        if (tid < 128) {
            int bb = tid >> 1, hf = tid & 1;
            uint2 vh = *(const uint2*)&osh[bb * 4 + hf * 2];
            uint2 vl = *(const uint2*)&osl[bb * 4 + hf * 2];
            *(uint2*)(dHi + (size_t)bb * PU + ubase + hf * 4) = vh;
            *(uint2*)(dLo + (size_t)bb * PU + ubase + hf * 4) = vl;
        }

        // ---- barrier ARRIVE ----
        __syncthreads();
        unsigned snap = 0;
        if (tid == 0) {
            __threadfence();
            snap = *((volatile unsigned*)&g_bar_gen);
            unsigned prev = atomicAdd(&g_bar_count, 1u);
            if (prev == NBLK - 1u) {
                atomicExch(&g_bar_count, 0u);
                __threadfence();
                atomicAdd(&g_bar_gen, 1u);
            }
        }

        // ---- overlapped with barrier wait: out store + next-step prefetch ----
        if (tid < 128) {
            int bb = tid >> 1, hf = tid & 1;
            float4 v = *(const float4*)&os[bb * 8 + hf * 4];
            *(float4*)(out + ((size_t)bb * PT + t) * PU + ubase + hf * 4) = v;
            if (t == PT - 1 && hlast != nullptr)
                *(float4*)(hlast + (size_t)bb * PU + ubase + hf * 4) = v;
        }
        if (t < PT - 1) {
            const float* xrow = xp + ((size_t)(t + 1) * PB + eb) * PC3 + ubase + uo * 2;
            xz = *(const float2*)(xrow);
            xr = *(const float2*)(xrow + PU);
            xh = *(const float2*)(xrow + 2 * PU);
            hp = *(const float2*)&os[eb * 8 + uo * 2];
        }

        // ---- barrier WAIT ----
        if (tid == 0) {
            while (*((volatile unsigned*)&g_bar_gen) == snap) { }
            __threadfence();
        }
        __syncthreads();
    }
}

// ---------------------------------------------------------------------------
// launch
// ---------------------------------------------------------------------------
extern "C" void kernel_launch(void* const* d_in, const int* in_sizes, int n_in,
                              void* d_out, int out_size)
{
    const int*   x       = (const int*)  d_in[0];
    const float* initial = (const float*)d_in[1];
    const float* emb     = (const float*)d_in[2];
    const float* Win     = (const float*)d_in[3];
    const float* Wrec    = (const float*)d_in[4];
    const float* bin     = (const float*)d_in[5];
    const float* brec    = (const float*)d_in[6];

    float* out = (float*)d_out;
    float* hlast = nullptr;
    const long long n_outputs = (long long)PB * PT * PU;
    if ((long long)out_size >= n_outputs + (long long)PB * PU) {
        hlast = out + (size_t)n_outputs;
    }

    float* xp = nullptr;
    cudaGetSymbolAddress((void**)&xp, g_xp);
    __nv_bfloat16 *hhi, *hlo, *embh, *embl, *winth, *wintl;
    cudaGetSymbolAddress((void**)&hhi, g_hhi);
    cudaGetSymbolAddress((void**)&hlo, g_hlo);
    cudaGetSymbolAddress((void**)&embh, g_embh);
    cudaGetSymbolAddress((void**)&embl, g_embl);
    cudaGetSymbolAddress((void**)&winth, g_winth);
    cudaGetSymbolAddress((void**)&wintl, g_wintl);

    // prep: splits + transpose
    k_split_init<<<(PB * PU + 255) / 256, 256>>>(initial, hhi, hlo);
    k_prep_emb<<<(int)(((size_t)PV * PE / 4 + 255) / 256), 256>>>(emb, embh, embl);
    k_prep_winT<<<(PE * PC3 + 255) / 256, 256>>>(Win, winth, wintl);

    // GEMM1 on tensor cores
    cudaFuncSetAttribute(k_inproj_mma, cudaFuncAttributeMaxDynamicSharedMemorySize, IP_TOTAL);
    dim3 g1(PC3 / 128, (PT * PB) / 128);
    k_inproj_mma<<<g1, 256, IP_TOTAL>>>(x, embh, embl, winth, wintl, bin, xp);

    // persistent GRU scan
    cudaFuncSetAttribute(k_gru, cudaFuncAttributeMaxDynamicSharedMemorySize, SM_TOTAL);
    k_gru<<<NBLK, TPB, SM_TOTAL>>>(xp, initial, Wrec, brec, out, hlast);
}